// round 13
// baseline (speedup 1.0000x reference)
#include <cuda_runtime.h>
#include <cuda_bf16.h>

#define KNN  20
#define NB   4
#define NN   4096
#define NPT  (NB*NN)
#define NPK  (NPT*KNN)
#define NEG  0.2f
#define SCH  224                       // stat chunk (elements per chunk, = 7*32)

__device__ float  d_x0t[NPT*6];
__device__ int    d_nbr[NPK];
__device__ float  d_x1t[NPT*64];
__device__ float  d_x2t[NPT*64];
__device__ float  d_x3t[NPT*64];
__device__ float  d_bufA[(size_t)NPK*64];
__device__ float  d_bufB[(size_t)NPK*64];
__device__ float  d_gmaxv[NB*1024];
__device__ float  d_m[8*1024];
__device__ float  d_r[8*1024];
__device__ float  d_lanep[8*1024];     // per-(lane j, channel) partial sums

__device__ __forceinline__ float actf(float x, float m, float r, float g, float b){
    float t = __fadd_rn(x, -m);
    t = __fmul_rn(t, r);
    t = __fmul_rn(t, g);
    t = __fadd_rn(t, b);
    return t >= 0.f ? t : __fmul_rn(NEG, t);
}

__global__ void pack_kernel(const float* __restrict__ xyz, const float* __restrict__ feat){
    int i = blockIdx.x*blockDim.x + threadIdx.x;
    if (i >= NPT*6) return;
    int pn = i / 6, c = i % 6;
    int b = pn >> 12, n = pn & (NN-1);
    float v = (c < 3) ? xyz[((size_t)(b*3+c))*NN + n] : feat[((size_t)(b*3+c-3))*NN + n];
    d_x0t[i] = v;
}

// ---- BN stats: producer/consumer, identical arithmetic ------------------------
// Chain for (channel c, NEON lane j): sequential fp32 adds over elements
// idx == j (mod 8) of the (b,n,k)-linearized buffer, ascending. Unchanged.
// Block = 32 channels x 1 lane. Warp0 = consumer (32 chains, lockstep FADD);
// warps 1-7 = producers double-buffering 224-element chunks into shared.
__global__ __launch_bounds__(256) void bnstat1_kernel(const float* __restrict__ y, int C, int cnt, int l){
    extern __shared__ float buf[];     // [2][SCH*32]
    int t = threadIdx.x;
    int j = blockIdx.x & 7, cg = blockIdx.x >> 3;
    int c0 = cg*32;
    const float* base = y + (size_t)j*C + c0;
    size_t st = (size_t)8*C;
    int n = cnt >> 3;
    int nch = (n + SCH-1)/SCH;
    bool cons = (t < 32);
    int cx = t & 31;
    int iw = (t - 32) >> 5;            // producer sub-warp 0..6

    if (!cons){
        int len = n < SCH ? n : SCH;
        #pragma unroll
        for (int q = 0; q < 32; q++){
            int ii = iw + q*7;
            if (ii < len) buf[ii*32 + cx] = base[(size_t)ii*st + cx];
        }
    }
    __syncthreads();
    float s = 0.f;
    for (int ch = 0; ch < nch; ch++){
        int d = ch & 1;
        if (!cons){
            int i0 = (ch+1)*SCH;
            if (i0 < n){
                int len = (n - i0) < SCH ? (n - i0) : SCH;
                #pragma unroll
                for (int q = 0; q < 32; q++){
                    int ii = iw + q*7;
                    if (ii < len) buf[(d^1)*(SCH*32) + ii*32 + cx] = base[(size_t)(i0+ii)*st + cx];
                }
            }
        } else {
            int i0 = ch*SCH;
            int len = (n - i0) < SCH ? (n - i0) : SCH;
            const float* bb = buf + d*(SCH*32) + cx;
            #pragma unroll 8
            for (int ii = 0; ii < len; ii++)
                s = __fadd_rn(s, bb[ii*32]);
        }
        __syncthreads();
    }
    if (cons) d_lanep[j*1024 + c0 + cx] = s;
}

__global__ __launch_bounds__(256) void bnstat2_kernel(const float* __restrict__ y, int C, int cnt, int l){
    extern __shared__ float buf[];
    int t = threadIdx.x;
    int j = blockIdx.x & 7, cg = blockIdx.x >> 3;
    int c0 = cg*32;
    const float* base = y + (size_t)j*C + c0;
    size_t st = (size_t)8*C;
    int n = cnt >> 3;
    int nch = (n + SCH-1)/SCH;
    bool cons = (t < 32);
    int cx = t & 31;
    int iw = (t - 32) >> 5;
    float m = cons ? d_m[l*1024 + c0 + cx] : 0.f;

    if (!cons){
        int len = n < SCH ? n : SCH;
        #pragma unroll
        for (int q = 0; q < 32; q++){
            int ii = iw + q*7;
            if (ii < len) buf[ii*32 + cx] = base[(size_t)ii*st + cx];
        }
    }
    __syncthreads();
    float s = 0.f;
    for (int ch = 0; ch < nch; ch++){
        int d = ch & 1;
        if (!cons){
            int i0 = (ch+1)*SCH;
            if (i0 < n){
                int len = (n - i0) < SCH ? (n - i0) : SCH;
                #pragma unroll
                for (int q = 0; q < 32; q++){
                    int ii = iw + q*7;
                    if (ii < len) buf[(d^1)*(SCH*32) + ii*32 + cx] = base[(size_t)(i0+ii)*st + cx];
                }
            }
        } else {
            int i0 = ch*SCH;
            int len = (n - i0) < SCH ? (n - i0) : SCH;
            const float* bb = buf + d*(SCH*32) + cx;
            #pragma unroll 8
            for (int ii = 0; ii < len; ii++){
                float x = bb[ii*32];
                float dd = __fadd_rn(x, -m);
                s = __fadd_rn(s, __fmul_rn(dd, dd));
            }
        }
        __syncthreads();
    }
    if (cons) d_lanep[j*1024 + c0 + cx] = s;
}

// combiners: identical faddp tree ((a0+a4)+(a1+a5)) + ((a2+a6)+(a3+a7))
__global__ void bnfin1_kernel(int C, int cnt, int l){
    int c = blockIdx.x*blockDim.x + threadIdx.x;
    if (c >= C) return;
    float u0 = __fadd_rn(d_lanep[0*1024+c], d_lanep[4*1024+c]);
    float u1 = __fadd_rn(d_lanep[1*1024+c], d_lanep[5*1024+c]);
    float u2 = __fadd_rn(d_lanep[2*1024+c], d_lanep[6*1024+c]);
    float u3 = __fadd_rn(d_lanep[3*1024+c], d_lanep[7*1024+c]);
    float h0 = __fadd_rn(u0, u1);
    float h1 = __fadd_rn(u2, u3);
    float tot = __fadd_rn(h0, h1);
    d_m[l*1024 + c] = __fdiv_rn(tot, (float)cnt);
}

__global__ void bnfin2_kernel(int C, int cnt, int l){
    int c = blockIdx.x*blockDim.x + threadIdx.x;
    if (c >= C) return;
    float u0 = __fadd_rn(d_lanep[0*1024+c], d_lanep[4*1024+c]);
    float u1 = __fadd_rn(d_lanep[1*1024+c], d_lanep[5*1024+c]);
    float u2 = __fadd_rn(d_lanep[2*1024+c], d_lanep[6*1024+c]);
    float u3 = __fadd_rn(d_lanep[3*1024+c], d_lanep[7*1024+c]);
    float h0 = __fadd_rn(u0, u1);
    float h1 = __fadd_rn(u2, u3);
    float tot = __fadd_rn(h0, h1);
    float v = __fdiv_rn(tot, (float)cnt);
    d_r[l*1024 + c] = __fdiv_rn(1.f, __fsqrt_rn(__fadd_rn(v, 1e-5f)));
}

// ---- knn: unchanged (reference-order fp32) ------------------------------------
template<int C>
__global__ void __launch_bounds__(256) knn_kernel(const float* __restrict__ xt){
    extern __shared__ float sh[];
    float* qs = sh;
    float* ts = qs + C*33;
    float* dt = ts + C*129;
    float* tn = dt + 32*129;
    float* qn = tn + 128;
    float* mv = qn + 32;
    int*   mi = (int*)(mv + 32*8*KNN);

    int t  = threadIdx.x;
    int tx = t & 15, ty = t >> 4;
    int qbase = blockIdx.x * 32;
    int b = qbase >> 12;

    for (int e = t; e < 32*C; e += 256){
        int q = e / C, c = e % C;
        qs[c*33 + q] = xt[(size_t)(qbase + q)*C + c];
    }
    __syncthreads();
    if (t < 32){
        float s = 0.f;
        #pragma unroll
        for (int c = 0; c < C; c++){ float v = qs[c*33+t]; s = __fadd_rn(s, __fmul_rn(v,v)); }
        qn[t] = s;
    }

    int q = t >> 3, sub = t & 7;
    float bv[KNN]; int bi[KNN];
    #pragma unroll
    for (int u = 0; u < KNN; u++){ bv[u] = -3.4e38f; bi[u] = 0; }

    for (int m0 = 0; m0 < NN; m0 += 128){
        __syncthreads();
        for (int e = t; e < 128*C; e += 256){
            int ml = e / C, c = e % C;
            ts[c*129 + ml] = xt[(size_t)((b<<12) + m0 + ml)*C + c];
        }
        __syncthreads();
        if (t < 128){
            float s = 0.f;
            #pragma unroll
            for (int c = 0; c < C; c++){ float v = ts[c*129+t]; s = __fadd_rn(s, __fmul_rn(v,v)); }
            tn[t] = s;
        }
        __syncthreads();

        float acc0[8], acc1[8];
        #pragma unroll
        for (int j = 0; j < 8; j++){ acc0[j] = 0.f; acc1[j] = 0.f; }
        #pragma unroll 2
        for (int c = 0; c < C; c++){
            float qv0 = qs[c*33 + ty];
            float qv1 = qs[c*33 + ty + 16];
            #pragma unroll
            for (int j = 0; j < 8; j++){
                float m = ts[c*129 + tx + 16*j];
                acc0[j] = fmaf(qv0, m, acc0[j]);
                acc1[j] = fmaf(qv1, m, acc1[j]);
            }
        }
        {
            float qn0 = qn[ty], qn1 = qn[ty+16];
            #pragma unroll
            for (int j = 0; j < 8; j++){
                int mm = tx + 16*j;
                float tnm = tn[mm];
                dt[(ty)   *129 + mm] = __fadd_rn(fmaf(2.f, acc0[j], -qn0), -tnm);
                dt[(ty+16)*129 + mm] = __fadd_rn(fmaf(2.f, acc1[j], -qn1), -tnm);
            }
        }
        __syncthreads();

        #pragma unroll
        for (int j = 0; j < 16; j++){
            int ml = sub + 8*j;
            float v = dt[q*129 + ml];
            if (v > bv[KNN-1]){
                float cv = v; int ci = m0 + ml;
                #pragma unroll
                for (int u = 0; u < KNN; u++){
                    if (cv > bv[u]){
                        float tf = bv[u]; bv[u] = cv; cv = tf;
                        int   ti = bi[u]; bi[u] = ci; ci = ti;
                    }
                }
            }
        }
    }
    __syncthreads();
    {
        int base = (q*8 + sub)*KNN;
        #pragma unroll
        for (int u = 0; u < KNN; u++){ mv[base+u] = bv[u]; mi[base+u] = bi[u]; }
    }
    __syncthreads();
    if (sub == 0){
        int* hd = (int*)dt + q*8;
        #pragma unroll
        for (int j = 0; j < 8; j++) hd[j] = 0;
        for (int u = 0; u < KNN; u++){
            float best = -3.4e38f; int bidx = 0x7fffffff; int bl = 0;
            #pragma unroll
            for (int j = 0; j < 8; j++){
                int h = hd[j];
                if (h < KNN){
                    float av = mv[(q*8+j)*KNN + h];
                    int   ai = mi[(q*8+j)*KNN + h];
                    if (av > best || (av == best && ai < bidx)){ best = av; bidx = ai; bl = j; }
                }
            }
            d_nbr[(size_t)(qbase + q)*KNN + u] = bidx;
            hd[bl] = hd[bl] + 1;
        }
    }
}

// ---- tiled 1x1 conv, plain ascending-k fmaf (R10-proven) ----------------------
#define CTM 64
#define CTP 128
#define CKB 64

template<int MODE>
__global__ void __launch_bounds__(128) conv_kernel(
    const float* __restrict__ W, int Ktot, int Ototal,
    const float* __restrict__ in0, const float* __restrict__ in1,
    const float* __restrict__ in2, const float* __restrict__ in3,
    const float* __restrict__ ga, const float* __restrict__ ba,
    int Chalf, int actLayer, float* __restrict__ out)
{
    extern __shared__ float sh[];
    float* Ws = sh;
    float* Xs = sh + CKB*65;
    __shared__ int snbr[CTP];
    int t  = threadIdx.x;
    int tx = t & 15, ty = t >> 4;
    int gpBase = blockIdx.x * CTP;
    int oBase  = blockIdx.y * CTM;

    if (MODE == 0){
        if (t < 128) snbr[t] = d_nbr[gpBase + t];
    }

    float acc[8][8];
    #pragma unroll
    for (int i = 0; i < 8; i++)
        #pragma unroll
        for (int j = 0; j < 8; j++) acc[i][j] = 0.f;

    int nchunk = (Ktot + CKB - 1) / CKB;
    for (int ch = 0; ch < nchunk; ch++){
        int kc0 = ch * CKB;
        __syncthreads();
        for (int e = t; e < CKB*CTM; e += 128){
            int o = e >> 6, c = e & 63;
            int kc = kc0 + c;
            Ws[c*65 + o] = (kc < Ktot) ? W[(size_t)(oBase+o)*Ktot + kc] : 0.f;
        }
        for (int e = t; e < CKB*CTP; e += 128){
            int p = e >> 6, c = e & 63;
            int kc = kc0 + c;
            float v = 0.f;
            if (kc < Ktot){
                int gp = gpBase + p;
                if (MODE == 0){
                    int pn = gp / 20;
                    int bb = pn >> 12;
                    if (kc < Chalf){
                        int m = snbr[p];
                        v = in0[(size_t)((bb<<12) + m)*Chalf + kc];
                    } else {
                        v = in0[(size_t)pn*Chalf + (kc - Chalf)];
                    }
                } else if (MODE == 1){
                    float rr = in0[(size_t)gp*Ktot + kc];
                    v = actf(rr, d_m[actLayer*1024+kc], d_r[actLayer*1024+kc], ga[kc], ba[kc]);
                } else if (MODE == 2){
                    const float* src = (kc < 64) ? in0 : ((kc < 128) ? in1 : in2);
                    v = src[(size_t)gp*64 + (kc & 63)];
                } else {
                    if (kc < 1024){
                        int bb = gp >> 12;
                        v = in3[bb*1024 + kc];
                    } else {
                        int c2 = kc - 1024;
                        const float* src = (c2 < 64) ? in0 : ((c2 < 128) ? in1 : in2);
                        v = src[(size_t)gp*64 + (c2 & 63)];
                    }
                }
            }
            Xs[c*129 + p] = v;
        }
        __syncthreads();
        #pragma unroll 4
        for (int k = 0; k < CKB; k++){
            float xv[8], wv[8];
            #pragma unroll
            for (int j = 0; j < 8; j++) xv[j] = Xs[k*129 + tx + 16*j];
            #pragma unroll
            for (int i = 0; i < 8; i++) wv[i] = Ws[k*65 + ty + 8*i];
            #pragma unroll
            for (int i = 0; i < 8; i++)
                #pragma unroll
                for (int j = 0; j < 8; j++)
                    acc[i][j] = fmaf(wv[i], xv[j], acc[i][j]);
        }
    }

    __syncthreads();
    float* outS = sh;
    #pragma unroll
    for (int j = 0; j < 8; j++)
        #pragma unroll
        for (int i = 0; i < 8; i++)
            outS[(tx + 16*j)*65 + ty + 8*i] = acc[i][j];
    __syncthreads();
    for (int e = t; e < CTP*CTM; e += 128){
        int p = e >> 6, o = e & 63;
        out[(size_t)(gpBase+p)*Ototal + oBase + o] = outS[p*65 + o];
    }
}

__global__ void maxk_kernel(const float* __restrict__ y, int l,
                            const float* __restrict__ gl, const float* __restrict__ bl,
                            float* __restrict__ xt){
    int t = threadIdx.x;
    int p = blockIdx.x*4 + (t >> 6);
    int o = t & 63;
    float m = d_m[l*1024+o], r = d_r[l*1024+o];
    float gv = gl[o], bvv = bl[o];
    const float* base = y + (size_t)p*KNN*64 + o;
    float mx = -3.4e38f;
    #pragma unroll
    for (int kk = 0; kk < KNN; kk++){
        float v = actf(base[kk*64], m, r, gv, bvv);
        mx = fmaxf(mx, v);
    }
    xt[(size_t)p*64 + o] = mx;
}

__global__ void gmax_kernel(const float* __restrict__ y6, int l,
                            const float* __restrict__ gl, const float* __restrict__ bl){
    int bb = blockIdx.x >> 4, grp = blockIdx.x & 15;
    int t = threadIdx.x;
    int o = grp*64 + (t & 63);
    float m = d_m[l*1024+o], r = d_r[l*1024+o];
    float gv = gl[o], bvv = bl[o];
    float mx = -3.4e38f;
    for (int n = (t >> 6); n < NN; n += 4){
        float v = actf(y6[((size_t)(bb*NN+n))*1024 + o], m, r, gv, bvv);
        mx = fmaxf(mx, v);
    }
    __shared__ float red[256];
    red[t] = mx;
    __syncthreads();
    if (t < 64){
        float mm = fmaxf(fmaxf(red[t], red[t+64]), fmaxf(red[t+128], red[t+192]));
        d_gmaxv[bb*1024 + o] = mm;
    }
}

__global__ void __launch_bounds__(128) final_kernel(const float* __restrict__ W9,
                                                    const float* __restrict__ y8,
                                                    const float* __restrict__ gl,
                                                    const float* __restrict__ bl,
                                                    float* __restrict__ out){
    __shared__ float Ws[13*64];
    __shared__ float Xs[64*129];
    int t = threadIdx.x;
    int pBase = blockIdx.x * 128;
    float acc[13];
    #pragma unroll
    for (int o = 0; o < 13; o++) acc[o] = 0.f;

    for (int ch = 0; ch < 4; ch++){
        __syncthreads();
        for (int e = t; e < 13*64; e += 128){
            int o = e >> 6, c = e & 63;
            Ws[e] = W9[o*256 + ch*64 + c];
        }
        for (int e = t; e < 64*128; e += 128){
            int p = e >> 6, c = e & 63;
            int kc = ch*64 + c;
            float rr = y8[(size_t)(pBase+p)*256 + kc];
            Xs[c*129 + p] = actf(rr, d_m[7*1024 + kc], d_r[7*1024 + kc], gl[kc], bl[kc]);
        }
        __syncthreads();
        #pragma unroll 4
        for (int k = 0; k < 64; k++){
            float xv = Xs[k*129 + t];
            #pragma unroll
            for (int o = 0; o < 13; o++)
                acc[o] = fmaf(Ws[o*64 + k], xv, acc[o]);
        }
    }
    int pn = pBase + t;
    int b = pn >> 12, n = pn & (NN-1);
    #pragma unroll
    for (int o = 0; o < 13; o++)
        out[(size_t)b*13*NN + (size_t)o*NN + n] = acc[o];
}

extern "C" void kernel_launch(void* const* d_in, const int* in_sizes, int n_in,
                              void* d_out, int out_size) {
    const float* xyz  = (const float*)d_in[0];
    const float* feat = (const float*)d_in[1];
    const float* W1 = (const float*)d_in[2];
    const float* W2 = (const float*)d_in[3];
    const float* W3 = (const float*)d_in[4];
    const float* W4 = (const float*)d_in[5];
    const float* W5 = (const float*)d_in[6];
    const float* W6 = (const float*)d_in[7];
    const float* W7 = (const float*)d_in[8];
    const float* W8 = (const float*)d_in[9];
    const float* W9 = (const float*)d_in[10];
    const float* g[8]; const float* bb[8];
    for (int i = 0; i < 8; i++){ g[i] = (const float*)d_in[11+2*i]; bb[i] = (const float*)d_in[12+2*i]; }
    float* out = (float*)d_out;

    float *x0t, *x1t, *x2t, *x3t, *bufA, *bufB, *gmx;
    cudaGetSymbolAddress((void**)&x0t,  d_x0t);
    cudaGetSymbolAddress((void**)&x1t,  d_x1t);
    cudaGetSymbolAddress((void**)&x2t,  d_x2t);
    cudaGetSymbolAddress((void**)&x3t,  d_x3t);
    cudaGetSymbolAddress((void**)&bufA, d_bufA);
    cudaGetSymbolAddress((void**)&bufB, d_bufB);
    cudaGetSymbolAddress((void**)&gmx,  d_gmaxv);

    const int SH_KNN6  = (6*33  + 6*129  + 32*129 + 32*8*KNN)*4 + 32*8*KNN*4 + (128+32)*4;
    const int SH_KNN64 = (64*33 + 64*129 + 32*129 + 32*8*KNN)*4 + 32*8*KNN*4 + (128+32)*4;
    const int SH_CONV  = (CKB*65 + CKB*129)*4;
    const int SH_STAT  = 2*SCH*32*4;   // 57344

    cudaFuncSetAttribute(knn_kernel<6>,  cudaFuncAttributeMaxDynamicSharedMemorySize, SH_KNN6);
    cudaFuncSetAttribute(knn_kernel<64>, cudaFuncAttributeMaxDynamicSharedMemorySize, SH_KNN64);
    cudaFuncSetAttribute(conv_kernel<0>, cudaFuncAttributeMaxDynamicSharedMemorySize, SH_CONV);
    cudaFuncSetAttribute(conv_kernel<1>, cudaFuncAttributeMaxDynamicSharedMemorySize, SH_CONV);
    cudaFuncSetAttribute(conv_kernel<2>, cudaFuncAttributeMaxDynamicSharedMemorySize, SH_CONV);
    cudaFuncSetAttribute(conv_kernel<3>, cudaFuncAttributeMaxDynamicSharedMemorySize, SH_CONV);
    cudaFuncSetAttribute(bnstat1_kernel, cudaFuncAttributeMaxDynamicSharedMemorySize, SH_STAT);
    cudaFuncSetAttribute(bnstat2_kernel, cudaFuncAttributeMaxDynamicSharedMemorySize, SH_STAT);

    dim3 gEdge(NPK/CTP, 1);

    pack_kernel<<<(NPT*6+255)/256, 256>>>(xyz, feat);

    #define BNSTATS(buf_, C_, cnt_, l_) \
        bnstat1_kernel<<<(C_/32)*8, 256, SH_STAT>>>(buf_, C_, cnt_, l_); \
        bnfin1_kernel<<<(C_+63)/64, 64>>>(C_, cnt_, l_); \
        bnstat2_kernel<<<(C_/32)*8, 256, SH_STAT>>>(buf_, C_, cnt_, l_); \
        bnfin2_kernel<<<(C_+63)/64, 64>>>(C_, cnt_, l_)

    knn_kernel<6><<<NPT/32, 256, SH_KNN6>>>(x0t);
    conv_kernel<0><<<gEdge, 128, SH_CONV>>>(W1, 12, 64, x0t, 0,0,0, 0,0, 6, 0, bufA);
    BNSTATS(bufA, 64, NPK, 0);
    conv_kernel<1><<<gEdge, 128, SH_CONV>>>(W2, 64, 64, bufA, 0,0,0, g[0], bb[0], 0, 0, bufB);
    BNSTATS(bufB, 64, NPK, 1);
    maxk_kernel<<<NPT/4, 256>>>(bufB, 1, g[1], bb[1], x1t);

    knn_kernel<64><<<NPT/32, 256, SH_KNN64>>>(x1t);
    conv_kernel<0><<<gEdge, 128, SH_CONV>>>(W3, 128, 64, x1t, 0,0,0, 0,0, 64, 0, bufA);
    BNSTATS(bufA, 64, NPK, 2);
    conv_kernel<1><<<gEdge, 128, SH_CONV>>>(W4, 64, 64, bufA, 0,0,0, g[2], bb[2], 0, 2, bufB);
    BNSTATS(bufB, 64, NPK, 3);
    maxk_kernel<<<NPT/4, 256>>>(bufB, 3, g[3], bb[3], x2t);

    knn_kernel<64><<<NPT/32, 256, SH_KNN64>>>(x2t);
    conv_kernel<0><<<gEdge, 128, SH_CONV>>>(W5, 128, 64, x2t, 0,0,0, 0,0, 64, 0, bufA);
    BNSTATS(bufA, 64, NPK, 4);
    maxk_kernel<<<NPT/4, 256>>>(bufA, 4, g[4], bb[4], x3t);

    conv_kernel<2><<<dim3(NPT/CTP, 16), 128, SH_CONV>>>(W6, 192, 1024, x1t, x2t, x3t, 0, 0,0, 0, 0, bufB);
    BNSTATS(bufB, 1024, NPT, 5);
    gmax_kernel<<<NB*16, 256>>>(bufB, 5, g[5], bb[5]);

    conv_kernel<3><<<dim3(NPT/CTP, 8), 128, SH_CONV>>>(W7, 1216, 512, x1t, x2t, x3t, gmx, 0,0, 0, 0, bufA);
    BNSTATS(bufA, 512, NPT, 6);
    conv_kernel<1><<<dim3(NPT/CTP, 4), 128, SH_CONV>>>(W8, 512, 256, bufA, 0,0,0, g[6], bb[6], 0, 6, bufB);
    BNSTATS(bufB, 256, NPT, 7);
    final_kernel<<<NPT/128, 128>>>(W9, bufB, g[7], bb[7], out);
}

// round 14
// speedup vs baseline: 2.6865x; 2.6865x over previous
#include <cuda_runtime.h>
#include <cuda_bf16.h>

#define KNN  20
#define NB   4
#define NN   4096
#define NPT  (NB*NN)
#define NPK  (NPT*KNN)
#define NEG  0.2f

__device__ float  d_x0t[NPT*6];
__device__ int    d_nbr[NPK];
__device__ float  d_x1t[NPT*64];
__device__ float  d_x2t[NPT*64];
__device__ float  d_x3t[NPT*64];
__device__ float  d_bufA[(size_t)NPK*64];
__device__ float  d_bufB[(size_t)NPK*64];
__device__ float  d_gmaxv[NB*1024];
__device__ float  d_m[8*1024];
__device__ float  d_r[8*1024];

__device__ __forceinline__ float actf(float x, float m, float r, float g, float b){
    float t = __fadd_rn(x, -m);
    t = __fmul_rn(t, r);
    t = __fmul_rn(t, g);
    t = __fadd_rn(t, b);
    return t >= 0.f ? t : __fmul_rn(NEG, t);
}

__global__ void pack_kernel(const float* __restrict__ xyz, const float* __restrict__ feat){
    int i = blockIdx.x*blockDim.x + threadIdx.x;
    if (i >= NPT*6) return;
    int pn = i / 6, c = i % 6;
    int b = pn >> 12, n = pn & (NN-1);
    float v = (c < 3) ? xyz[((size_t)(b*3+c))*NN + n] : feat[((size_t)(b*3+c-3))*NN + n];
    d_x0t[i] = v;
}

// ---- BN stats: 8 NEON lanes per channel, shfl-relay, software-pipelined ------
// Identical arithmetic to the 9.47ms R10 kernel: lane j sums elements
// idx == j (mod 8) in ascending order with one sequential fp32 accumulator;
// groups of 32 relayed via shfl in ascending hw-lane order; lanes combined
// with the faddp tree ((a0+a4)+(a1+a5)) + ((a2+a6)+(a3+a7)).
// Pipelining: 2-group unroll, independent shfl batches (tA/tB) issue in the
// spare slots between the dependent FADDs. nG is even for all layers.
__global__ void __launch_bounds__(256) bnstat1_kernel(const float* __restrict__ y, int C, int cnt, int l){
    __shared__ float lpart[8];
    int j = threadIdx.x >> 5;        // NEON lane (warp) 0..7
    int u = threadIdx.x & 31;        // hw lane
    int c = blockIdx.x;              // channel
    const float* qp = y + (size_t)(u*8 + j)*C + c;
    size_t gs = (size_t)256*C;       // group stride: 32 elems * 8 lanes * C
    int nG = (cnt >> 3) >> 5;        // groups of 32 per chain (even by construction)
    float a = qp[0];
    float b = (nG > 1) ? qp[gs] : 0.f;
    float s = 0.f;
    float tA[32], tB[32];
    #pragma unroll
    for (int uu = 0; uu < 32; uu++) tA[uu] = __shfl_sync(0xffffffffu, a, uu);
    for (int g = 0; g < nG; g += 2){
        float nx0 = (g+2 < nG) ? qp[(size_t)(g+2)*gs] : 0.f;
        float nx1 = (g+3 < nG) ? qp[(size_t)(g+3)*gs] : 0.f;
        #pragma unroll
        for (int uu = 0; uu < 32; uu++) tB[uu] = __shfl_sync(0xffffffffu, b, uu);
        #pragma unroll
        for (int uu = 0; uu < 32; uu++) s = __fadd_rn(s, tA[uu]);   // group g
        #pragma unroll
        for (int uu = 0; uu < 32; uu++) tA[uu] = __shfl_sync(0xffffffffu, nx0, uu);
        #pragma unroll
        for (int uu = 0; uu < 32; uu++) s = __fadd_rn(s, tB[uu]);   // group g+1
        b = nx1;
    }
    if (u == 0) lpart[j] = s;
    __syncthreads();
    if (threadIdx.x == 0){
        float u0 = __fadd_rn(lpart[0], lpart[4]);
        float u1 = __fadd_rn(lpart[1], lpart[5]);
        float u2 = __fadd_rn(lpart[2], lpart[6]);
        float u3 = __fadd_rn(lpart[3], lpart[7]);
        float h0 = __fadd_rn(u0, u1);
        float h1 = __fadd_rn(u2, u3);
        float tot = __fadd_rn(h0, h1);
        d_m[l*1024 + c] = __fdiv_rn(tot, (float)cnt);
    }
}

__global__ void __launch_bounds__(256) bnstat2_kernel(const float* __restrict__ y, int C, int cnt, int l){
    __shared__ float lpart[8];
    int j = threadIdx.x >> 5;
    int u = threadIdx.x & 31;
    int c = blockIdx.x;
    const float* qp = y + (size_t)(u*8 + j)*C + c;
    size_t gs = (size_t)256*C;
    int nG = (cnt >> 3) >> 5;
    float m = d_m[l*1024 + c];
    float a = qp[0];
    float b = (nG > 1) ? qp[gs] : 0.f;
    float s = 0.f;
    float tA[32], tB[32];
    {
        float da = __fadd_rn(a, -m);
        float sqa = __fmul_rn(da, da);
        #pragma unroll
        for (int uu = 0; uu < 32; uu++) tA[uu] = __shfl_sync(0xffffffffu, sqa, uu);
    }
    for (int g = 0; g < nG; g += 2){
        float nx0 = (g+2 < nG) ? qp[(size_t)(g+2)*gs] : 0.f;
        float nx1 = (g+3 < nG) ? qp[(size_t)(g+3)*gs] : 0.f;
        float db = __fadd_rn(b, -m);
        float sqb = __fmul_rn(db, db);
        #pragma unroll
        for (int uu = 0; uu < 32; uu++) tB[uu] = __shfl_sync(0xffffffffu, sqb, uu);
        #pragma unroll
        for (int uu = 0; uu < 32; uu++) s = __fadd_rn(s, tA[uu]);   // group g
        float dn = __fadd_rn(nx0, -m);
        float sqn = __fmul_rn(dn, dn);
        #pragma unroll
        for (int uu = 0; uu < 32; uu++) tA[uu] = __shfl_sync(0xffffffffu, sqn, uu);
        #pragma unroll
        for (int uu = 0; uu < 32; uu++) s = __fadd_rn(s, tB[uu]);   // group g+1
        b = nx1;
    }
    if (u == 0) lpart[j] = s;
    __syncthreads();
    if (threadIdx.x == 0){
        float u0 = __fadd_rn(lpart[0], lpart[4]);
        float u1 = __fadd_rn(lpart[1], lpart[5]);
        float u2 = __fadd_rn(lpart[2], lpart[6]);
        float u3 = __fadd_rn(lpart[3], lpart[7]);
        float h0 = __fadd_rn(u0, u1);
        float h1 = __fadd_rn(u2, u3);
        float tot = __fadd_rn(h0, h1);
        float v = __fdiv_rn(tot, (float)cnt);
        d_r[l*1024 + c] = __fdiv_rn(1.f, __fsqrt_rn(__fadd_rn(v, 1e-5f)));
    }
}

// ---- knn: same distances; register top-20 (static idx) + shared 8-way merge --
template<int C>
__global__ void __launch_bounds__(256) knn_kernel(const float* __restrict__ xt){
    extern __shared__ float sh[];
    float* qs = sh;
    float* ts = qs + C*33;
    float* dt = ts + C*129;
    float* tn = dt + 32*129;
    float* qn = tn + 128;
    float* mv = qn + 32;
    int*   mi = (int*)(mv + 32*8*KNN);

    int t  = threadIdx.x;
    int tx = t & 15, ty = t >> 4;
    int qbase = blockIdx.x * 32;
    int b = qbase >> 12;

    for (int e = t; e < 32*C; e += 256){
        int q = e / C, c = e % C;
        qs[c*33 + q] = xt[(size_t)(qbase + q)*C + c];
    }
    __syncthreads();
    if (t < 32){
        float s = 0.f;
        #pragma unroll
        for (int c = 0; c < C; c++){ float v = qs[c*33+t]; s = __fadd_rn(s, __fmul_rn(v,v)); }
        qn[t] = s;
    }

    int q = t >> 3, sub = t & 7;
    float bv[KNN]; int bi[KNN];
    #pragma unroll
    for (int u = 0; u < KNN; u++){ bv[u] = -3.4e38f; bi[u] = 0; }

    for (int m0 = 0; m0 < NN; m0 += 128){
        __syncthreads();
        for (int e = t; e < 128*C; e += 256){
            int ml = e / C, c = e % C;
            ts[c*129 + ml] = xt[(size_t)((b<<12) + m0 + ml)*C + c];
        }
        __syncthreads();
        if (t < 128){
            float s = 0.f;
            #pragma unroll
            for (int c = 0; c < C; c++){ float v = ts[c*129+t]; s = __fadd_rn(s, __fmul_rn(v,v)); }
            tn[t] = s;
        }
        __syncthreads();

        float acc0[8], acc1[8];
        #pragma unroll
        for (int j = 0; j < 8; j++){ acc0[j] = 0.f; acc1[j] = 0.f; }
        #pragma unroll 2
        for (int c = 0; c < C; c++){
            float qv0 = qs[c*33 + ty];
            float qv1 = qs[c*33 + ty + 16];
            #pragma unroll
            for (int j = 0; j < 8; j++){
                float m = ts[c*129 + tx + 16*j];
                acc0[j] = fmaf(qv0, m, acc0[j]);
                acc1[j] = fmaf(qv1, m, acc1[j]);
            }
        }
        {
            float qn0 = qn[ty], qn1 = qn[ty+16];
            #pragma unroll
            for (int j = 0; j < 8; j++){
                int mm = tx + 16*j;
                float tnm = tn[mm];
                dt[(ty)   *129 + mm] = __fadd_rn(fmaf(2.f, acc0[j], -qn0), -tnm);
                dt[(ty+16)*129 + mm] = __fadd_rn(fmaf(2.f, acc1[j], -qn1), -tnm);
            }
        }
        __syncthreads();

        #pragma unroll
        for (int j = 0; j < 16; j++){
            int ml = sub + 8*j;
            float v = dt[q*129 + ml];
            if (v > bv[KNN-1]){
                float cv = v; int ci = m0 + ml;
                #pragma unroll
                for (int u = 0; u < KNN; u++){
                    if (cv > bv[u]){
                        float tf = bv[u]; bv[u] = cv; cv = tf;
                        int   ti = bi[u]; bi[u] = ci; ci = ti;
                    }
                }
            }
        }
    }
    __syncthreads();
    {
        int base = (q*8 + sub)*KNN;
        #pragma unroll
        for (int u = 0; u < KNN; u++){ mv[base+u] = bv[u]; mi[base+u] = bi[u]; }
    }
    __syncthreads();
    if (sub == 0){
        int* hd = (int*)dt + q*8;
        #pragma unroll
        for (int j = 0; j < 8; j++) hd[j] = 0;
        for (int u = 0; u < KNN; u++){
            float best = -3.4e38f; int bidx = 0x7fffffff; int bl = 0;
            #pragma unroll
            for (int j = 0; j < 8; j++){
                int h = hd[j];
                if (h < KNN){
                    float av = mv[(q*8+j)*KNN + h];
                    int   ai = mi[(q*8+j)*KNN + h];
                    if (av > best || (av == best && ai < bidx)){ best = av; bidx = ai; bl = j; }
                }
            }
            d_nbr[(size_t)(qbase + q)*KNN + u] = bidx;
            hd[bl] = hd[bl] + 1;
        }
    }
}

// ---- tiled 1x1 conv, plain ascending-k fmaf (R10-proven) ----------------------
#define CTM 64
#define CTP 128
#define CKB 64

template<int MODE>
__global__ void __launch_bounds__(128) conv_kernel(
    const float* __restrict__ W, int Ktot, int Ototal,
    const float* __restrict__ in0, const float* __restrict__ in1,
    const float* __restrict__ in2, const float* __restrict__ in3,
    const float* __restrict__ ga, const float* __restrict__ ba,
    int Chalf, int actLayer, float* __restrict__ out)
{
    extern __shared__ float sh[];
    float* Ws = sh;
    float* Xs = sh + CKB*65;
    __shared__ int snbr[CTP];
    int t  = threadIdx.x;
    int tx = t & 15, ty = t >> 4;
    int gpBase = blockIdx.x * CTP;
    int oBase  = blockIdx.y * CTM;

    if (MODE == 0){
        if (t < 128) snbr[t] = d_nbr[gpBase + t];
    }

    float acc[8][8];
    #pragma unroll
    for (int i = 0; i < 8; i++)
        #pragma unroll
        for (int j = 0; j < 8; j++) acc[i][j] = 0.f;

    int nchunk = (Ktot + CKB - 1) / CKB;
    for (int ch = 0; ch < nchunk; ch++){
        int kc0 = ch * CKB;
        __syncthreads();
        for (int e = t; e < CKB*CTM; e += 128){
            int o = e >> 6, c = e & 63;
            int kc = kc0 + c;
            Ws[c*65 + o] = (kc < Ktot) ? W[(size_t)(oBase+o)*Ktot + kc] : 0.f;
        }
        for (int e = t; e < CKB*CTP; e += 128){
            int p = e >> 6, c = e & 63;
            int kc = kc0 + c;
            float v = 0.f;
            if (kc < Ktot){
                int gp = gpBase + p;
                if (MODE == 0){
                    int pn = gp / 20;
                    int bb = pn >> 12;
                    if (kc < Chalf){
                        int m = snbr[p];
                        v = in0[(size_t)((bb<<12) + m)*Chalf + kc];
                    } else {
                        v = in0[(size_t)pn*Chalf + (kc - Chalf)];
                    }
                } else if (MODE == 1){
                    float rr = in0[(size_t)gp*Ktot + kc];
                    v = actf(rr, d_m[actLayer*1024+kc], d_r[actLayer*1024+kc], ga[kc], ba[kc]);
                } else if (MODE == 2){
                    const float* src = (kc < 64) ? in0 : ((kc < 128) ? in1 : in2);
                    v = src[(size_t)gp*64 + (kc & 63)];
                } else {
                    if (kc < 1024){
                        int bb = gp >> 12;
                        v = in3[bb*1024 + kc];
                    } else {
                        int c2 = kc - 1024;
                        const float* src = (c2 < 64) ? in0 : ((c2 < 128) ? in1 : in2);
                        v = src[(size_t)gp*64 + (c2 & 63)];
                    }
                }
            }
            Xs[c*129 + p] = v;
        }
        __syncthreads();
        #pragma unroll 4
        for (int k = 0; k < CKB; k++){
            float xv[8], wv[8];
            #pragma unroll
            for (int j = 0; j < 8; j++) xv[j] = Xs[k*129 + tx + 16*j];
            #pragma unroll
            for (int i = 0; i < 8; i++) wv[i] = Ws[k*65 + ty + 8*i];
            #pragma unroll
            for (int i = 0; i < 8; i++)
                #pragma unroll
                for (int j = 0; j < 8; j++)
                    acc[i][j] = fmaf(wv[i], xv[j], acc[i][j]);
        }
    }

    __syncthreads();
    float* outS = sh;
    #pragma unroll
    for (int j = 0; j < 8; j++)
        #pragma unroll
        for (int i = 0; i < 8; i++)
            outS[(tx + 16*j)*65 + ty + 8*i] = acc[i][j];
    __syncthreads();
    for (int e = t; e < CTP*CTM; e += 128){
        int p = e >> 6, o = e & 63;
        out[(size_t)(gpBase+p)*Ototal + oBase + o] = outS[p*65 + o];
    }
}

__global__ void maxk_kernel(const float* __restrict__ y, int l,
                            const float* __restrict__ gl, const float* __restrict__ bl,
                            float* __restrict__ xt){
    int t = threadIdx.x;
    int p = blockIdx.x*4 + (t >> 6);
    int o = t & 63;
    float m = d_m[l*1024+o], r = d_r[l*1024+o];
    float gv = gl[o], bvv = bl[o];
    const float* base = y + (size_t)p*KNN*64 + o;
    float mx = -3.4e38f;
    #pragma unroll
    for (int kk = 0; kk < KNN; kk++){
        float v = actf(base[kk*64], m, r, gv, bvv);
        mx = fmaxf(mx, v);
    }
    xt[(size_t)p*64 + o] = mx;
}

__global__ void gmax_kernel(const float* __restrict__ y6, int l,
                            const float* __restrict__ gl, const float* __restrict__ bl){
    int bb = blockIdx.x >> 4, grp = blockIdx.x & 15;
    int t = threadIdx.x;
    int o = grp*64 + (t & 63);
    float m = d_m[l*1024+o], r = d_r[l*1024+o];
    float gv = gl[o], bvv = bl[o];
    float mx = -3.4e38f;
    for (int n = (t >> 6); n < NN; n += 4){
        float v = actf(y6[((size_t)(bb*NN+n))*1024 + o], m, r, gv, bvv);
        mx = fmaxf(mx, v);
    }
    __shared__ float red[256];
    red[t] = mx;
    __syncthreads();
    if (t < 64){
        float mm = fmaxf(fmaxf(red[t], red[t+64]), fmaxf(red[t+128], red[t+192]));
        d_gmaxv[bb*1024 + o] = mm;
    }
}

__global__ void __launch_bounds__(128) final_kernel(const float* __restrict__ W9,
                                                    const float* __restrict__ y8,
                                                    const float* __restrict__ gl,
                                                    const float* __restrict__ bl,
                                                    float* __restrict__ out){
    __shared__ float Ws[13*64];
    __shared__ float Xs[64*129];
    int t = threadIdx.x;
    int pBase = blockIdx.x * 128;
    float acc[13];
    #pragma unroll
    for (int o = 0; o < 13; o++) acc[o] = 0.f;

    for (int ch = 0; ch < 4; ch++){
        __syncthreads();
        for (int e = t; e < 13*64; e += 128){
            int o = e >> 6, c = e & 63;
            Ws[e] = W9[o*256 + ch*64 + c];
        }
        for (int e = t; e < 64*128; e += 128){
            int p = e >> 6, c = e & 63;
            int kc = ch*64 + c;
            float rr = y8[(size_t)(pBase+p)*256 + kc];
            Xs[c*129 + p] = actf(rr, d_m[7*1024 + kc], d_r[7*1024 + kc], gl[kc], bl[kc]);
        }
        __syncthreads();
        #pragma unroll 4
        for (int k = 0; k < 64; k++){
            float xv = Xs[k*129 + t];
            #pragma unroll
            for (int o = 0; o < 13; o++)
                acc[o] = fmaf(Ws[o*64 + k], xv, acc[o]);
        }
    }
    int pn = pBase + t;
    int b = pn >> 12, n = pn & (NN-1);
    #pragma unroll
    for (int o = 0; o < 13; o++)
        out[(size_t)b*13*NN + (size_t)o*NN + n] = acc[o];
}

extern "C" void kernel_launch(void* const* d_in, const int* in_sizes, int n_in,
                              void* d_out, int out_size) {
    const float* xyz  = (const float*)d_in[0];
    const float* feat = (const float*)d_in[1];
    const float* W1 = (const float*)d_in[2];
    const float* W2 = (const float*)d_in[3];
    const float* W3 = (const float*)d_in[4];
    const float* W4 = (const float*)d_in[5];
    const float* W5 = (const float*)d_in[6];
    const float* W6 = (const float*)d_in[7];
    const float* W7 = (const float*)d_in[8];
    const float* W8 = (const float*)d_in[9];
    const float* W9 = (const float*)d_in[10];
    const float* g[8]; const float* bb[8];
    for (int i = 0; i < 8; i++){ g[i] = (const float*)d_in[11+2*i]; bb[i] = (const float*)d_in[12+2*i]; }
    float* out = (float*)d_out;

    float *x0t, *x1t, *x2t, *x3t, *bufA, *bufB, *gmx;
    cudaGetSymbolAddress((void**)&x0t,  d_x0t);
    cudaGetSymbolAddress((void**)&x1t,  d_x1t);
    cudaGetSymbolAddress((void**)&x2t,  d_x2t);
    cudaGetSymbolAddress((void**)&x3t,  d_x3t);
    cudaGetSymbolAddress((void**)&bufA, d_bufA);
    cudaGetSymbolAddress((void**)&bufB, d_bufB);
    cudaGetSymbolAddress((void**)&gmx,  d_gmaxv);

    const int SH_KNN6  = (6*33  + 6*129  + 32*129 + 128 + 32 + 32*8*KNN)*4 + 32*8*KNN*4;
    const int SH_KNN64 = (64*33 + 64*129 + 32*129 + 128 + 32 + 32*8*KNN)*4 + 32*8*KNN*4;
    const int SH_CONV  = (CKB*65 + CKB*129)*4;

    cudaFuncSetAttribute(knn_kernel<6>,  cudaFuncAttributeMaxDynamicSharedMemorySize, SH_KNN6);
    cudaFuncSetAttribute(knn_kernel<64>, cudaFuncAttributeMaxDynamicSharedMemorySize, SH_KNN64);
    cudaFuncSetAttribute(conv_kernel<0>, cudaFuncAttributeMaxDynamicSharedMemorySize, SH_CONV);
    cudaFuncSetAttribute(conv_kernel<1>, cudaFuncAttributeMaxDynamicSharedMemorySize, SH_CONV);
    cudaFuncSetAttribute(conv_kernel<2>, cudaFuncAttributeMaxDynamicSharedMemorySize, SH_CONV);
    cudaFuncSetAttribute(conv_kernel<3>, cudaFuncAttributeMaxDynamicSharedMemorySize, SH_CONV);

    dim3 gEdge(NPK/CTP, 1);

    pack_kernel<<<(NPT*6+255)/256, 256>>>(xyz, feat);

    knn_kernel<6><<<NPT/32, 256, SH_KNN6>>>(x0t);
    conv_kernel<0><<<gEdge, 128, SH_CONV>>>(W1, 12, 64, x0t, 0,0,0, 0,0, 6, 0, bufA);
    bnstat1_kernel<<<64, 256>>>(bufA, 64, NPK, 0);
    bnstat2_kernel<<<64, 256>>>(bufA, 64, NPK, 0);
    conv_kernel<1><<<gEdge, 128, SH_CONV>>>(W2, 64, 64, bufA, 0,0,0, g[0], bb[0], 0, 0, bufB);
    bnstat1_kernel<<<64, 256>>>(bufB, 64, NPK, 1);
    bnstat2_kernel<<<64, 256>>>(bufB, 64, NPK, 1);
    maxk_kernel<<<NPT/4, 256>>>(bufB, 1, g[1], bb[1], x1t);

    knn_kernel<64><<<NPT/32, 256, SH_KNN64>>>(x1t);
    conv_kernel<0><<<gEdge, 128, SH_CONV>>>(W3, 128, 64, x1t, 0,0,0, 0,0, 64, 0, bufA);
    bnstat1_kernel<<<64, 256>>>(bufA, 64, NPK, 2);
    bnstat2_kernel<<<64, 256>>>(bufA, 64, NPK, 2);
    conv_kernel<1><<<gEdge, 128, SH_CONV>>>(W4, 64, 64, bufA, 0,0,0, g[2], bb[2], 0, 2, bufB);
    bnstat1_kernel<<<64, 256>>>(bufB, 64, NPK, 3);
    bnstat2_kernel<<<64, 256>>>(bufB, 64, NPK, 3);
    maxk_kernel<<<NPT/4, 256>>>(bufB, 3, g[3], bb[3], x2t);

    knn_kernel<64><<<NPT/32, 256, SH_KNN64>>>(x2t);
    conv_kernel<0><<<gEdge, 128, SH_CONV>>>(W5, 128, 64, x2t, 0,0,0, 0,0, 64, 0, bufA);
    bnstat1_kernel<<<64, 256>>>(bufA, 64, NPK, 4);
    bnstat2_kernel<<<64, 256>>>(bufA, 64, NPK, 4);
    maxk_kernel<<<NPT/4, 256>>>(bufA, 4, g[4], bb[4], x3t);

    conv_kernel<2><<<dim3(NPT/CTP, 16), 128, SH_CONV>>>(W6, 192, 1024, x1t, x2t, x3t, 0, 0,0, 0, 0, bufB);
    bnstat1_kernel<<<1024, 256>>>(bufB, 1024, NPT, 5);
    bnstat2_kernel<<<1024, 256>>>(bufB, 1024, NPT, 5);
    gmax_kernel<<<NB*16, 256>>>(bufB, 5, g[5], bb[5]);

    conv_kernel<3><<<dim3(NPT/CTP, 8), 128, SH_CONV>>>(W7, 1216, 512, x1t, x2t, x3t, gmx, 0,0, 0, 0, bufA);
    bnstat1_kernel<<<512, 256>>>(bufA, 512, NPT, 6);
    bnstat2_kernel<<<512, 256>>>(bufA, 512, NPT, 6);
    conv_kernel<1><<<dim3(NPT/CTP, 4), 128, SH_CONV>>>(W8, 512, 256, bufA, 0,0,0, g[6], bb[6], 0, 6, bufB);
    bnstat1_kernel<<<256, 256>>>(bufB, 256, NPT, 7);
    bnstat2_kernel<<<256, 256>>>(bufB, 256, NPT, 7);
    final_kernel<<<NPT/128, 128>>>(W9, bufB, g[7], bb[7], out);
}

// round 15
// speedup vs baseline: 2.8489x; 1.0604x over previous
#include <cuda_runtime.h>
#include <cuda_bf16.h>

#define KNN  20
#define NB   4
#define NN   4096
#define NPT  (NB*NN)
#define NPK  (NPT*KNN)
#define NEG  0.2f
#define SCH  256                       // stat chunk; 40960=160*256, 2048=8*256

__device__ float  d_x0t[NPT*6];
__device__ int    d_nbr[NPK];
__device__ float  d_x1t[NPT*64];
__device__ float  d_x2t[NPT*64];
__device__ float  d_x3t[NPT*64];
__device__ float  d_bufA[(size_t)NPK*64];
__device__ float  d_bufB[(size_t)NPK*64];
__device__ float  d_gmaxv[NB*1024];
__device__ float  d_m[8*1024];
__device__ float  d_r[8*1024];
__device__ float  d_lanep[8*1024];     // per-(lane j, channel) partial sums

__device__ __forceinline__ float actf(float x, float m, float r, float g, float b){
    float t = __fadd_rn(x, -m);
    t = __fmul_rn(t, r);
    t = __fmul_rn(t, g);
    t = __fadd_rn(t, b);
    return t >= 0.f ? t : __fmul_rn(NEG, t);
}

__global__ void pack_kernel(const float* __restrict__ xyz, const float* __restrict__ feat){
    int i = blockIdx.x*blockDim.x + threadIdx.x;
    if (i >= NPT*6) return;
    int pn = i / 6, c = i % 6;
    int b = pn >> 12, n = pn & (NN-1);
    float v = (c < 3) ? xyz[((size_t)(b*3+c))*NN + n] : feat[((size_t)(b*3+c-3))*NN + n];
    d_x0t[i] = v;
}

// ---- BN stats: producer/consumer, coalesced loads, pipelined consumer --------
// Chain (channel c, NEON lane j): sequential fp32 adds over elements
// idx == j (mod 8) of the (b,n,k)-linearized buffer, ascending (unchanged).
// Block = 32 channels x 1 lane (grid = (C/32)*8). Warp0 = consumer: 32 chains,
// one per thread; per 8 elements ptxas hoists 8 independent LDS ahead of the
// 8 dependent FADDs. Warps 1-7 = producers: double-buffer SCH-element chunks
// with fully coalesced 128B global loads. All chunks are exactly SCH long.
__global__ __launch_bounds__(256) void bnstat1_kernel(const float* __restrict__ y, int C, int cnt, int l){
    extern __shared__ float buf[];     // [2][SCH*32]
    int t = threadIdx.x;
    int j = blockIdx.x & 7, cg = blockIdx.x >> 3;
    int c0 = cg*32;
    const float* base = y + (size_t)j*C + c0;
    size_t st = (size_t)8*C;
    int n = cnt >> 3;                  // chain length, multiple of SCH
    int nch = n / SCH;
    bool cons = (t < 32);
    int cx = t & 31;
    int iw = (t - 32) >> 5;            // producer warp 0..6

    if (!cons){
        #pragma unroll
        for (int q = 0; q < 37; q++){
            int ii = iw + q*7;
            if (ii < SCH) buf[ii*32 + cx] = base[(size_t)ii*st + cx];
        }
    }
    __syncthreads();
    float s = 0.f;
    for (int ch = 0; ch < nch; ch++){
        int d = ch & 1;
        if (!cons){
            int i0 = (ch+1)*SCH;
            if (i0 < n){
                #pragma unroll
                for (int q = 0; q < 37; q++){
                    int ii = iw + q*7;
                    if (ii < SCH) buf[(d^1)*(SCH*32) + ii*32 + cx] = base[(size_t)(i0+ii)*st + cx];
                }
            }
        } else {
            const float* bb = buf + d*(SCH*32) + cx;
            #pragma unroll
            for (int ii = 0; ii < SCH; ii += 8){
                float v0 = bb[(ii+0)*32];
                float v1 = bb[(ii+1)*32];
                float v2 = bb[(ii+2)*32];
                float v3 = bb[(ii+3)*32];
                float v4 = bb[(ii+4)*32];
                float v5 = bb[(ii+5)*32];
                float v6 = bb[(ii+6)*32];
                float v7 = bb[(ii+7)*32];
                s = __fadd_rn(s, v0); s = __fadd_rn(s, v1);
                s = __fadd_rn(s, v2); s = __fadd_rn(s, v3);
                s = __fadd_rn(s, v4); s = __fadd_rn(s, v5);
                s = __fadd_rn(s, v6); s = __fadd_rn(s, v7);
            }
        }
        __syncthreads();
    }
    if (cons) d_lanep[j*1024 + c0 + cx] = s;
}

__global__ __launch_bounds__(256) void bnstat2_kernel(const float* __restrict__ y, int C, int cnt, int l){
    extern __shared__ float buf[];
    int t = threadIdx.x;
    int j = blockIdx.x & 7, cg = blockIdx.x >> 3;
    int c0 = cg*32;
    const float* base = y + (size_t)j*C + c0;
    size_t st = (size_t)8*C;
    int n = cnt >> 3;
    int nch = n / SCH;
    bool cons = (t < 32);
    int cx = t & 31;
    int iw = (t - 32) >> 5;
    float m = cons ? d_m[l*1024 + c0 + cx] : 0.f;

    if (!cons){
        #pragma unroll
        for (int q = 0; q < 37; q++){
            int ii = iw + q*7;
            if (ii < SCH) buf[ii*32 + cx] = base[(size_t)ii*st + cx];
        }
    }
    __syncthreads();
    float s = 0.f;
    for (int ch = 0; ch < nch; ch++){
        int d = ch & 1;
        if (!cons){
            int i0 = (ch+1)*SCH;
            if (i0 < n){
                #pragma unroll
                for (int q = 0; q < 37; q++){
                    int ii = iw + q*7;
                    if (ii < SCH) buf[(d^1)*(SCH*32) + ii*32 + cx] = base[(size_t)(i0+ii)*st + cx];
                }
            }
        } else {
            const float* bb = buf + d*(SCH*32) + cx;
            #pragma unroll
            for (int ii = 0; ii < SCH; ii += 8){
                float v0 = bb[(ii+0)*32];
                float v1 = bb[(ii+1)*32];
                float v2 = bb[(ii+2)*32];
                float v3 = bb[(ii+3)*32];
                float v4 = bb[(ii+4)*32];
                float v5 = bb[(ii+5)*32];
                float v6 = bb[(ii+6)*32];
                float v7 = bb[(ii+7)*32];
                float d0 = __fadd_rn(v0, -m); s = __fadd_rn(s, __fmul_rn(d0, d0));
                float d1 = __fadd_rn(v1, -m); s = __fadd_rn(s, __fmul_rn(d1, d1));
                float d2 = __fadd_rn(v2, -m); s = __fadd_rn(s, __fmul_rn(d2, d2));
                float d3 = __fadd_rn(v3, -m); s = __fadd_rn(s, __fmul_rn(d3, d3));
                float d4 = __fadd_rn(v4, -m); s = __fadd_rn(s, __fmul_rn(d4, d4));
                float d5 = __fadd_rn(v5, -m); s = __fadd_rn(s, __fmul_rn(d5, d5));
                float d6 = __fadd_rn(v6, -m); s = __fadd_rn(s, __fmul_rn(d6, d6));
                float d7 = __fadd_rn(v7, -m); s = __fadd_rn(s, __fmul_rn(d7, d7));
            }
        }
        __syncthreads();
    }
    if (cons) d_lanep[j*1024 + c0 + cx] = s;
}

// combiners: identical faddp tree ((a0+a4)+(a1+a5)) + ((a2+a6)+(a3+a7))
__global__ void bnfin1_kernel(int C, int cnt, int l){
    int c = blockIdx.x*blockDim.x + threadIdx.x;
    if (c >= C) return;
    float u0 = __fadd_rn(d_lanep[0*1024+c], d_lanep[4*1024+c]);
    float u1 = __fadd_rn(d_lanep[1*1024+c], d_lanep[5*1024+c]);
    float u2 = __fadd_rn(d_lanep[2*1024+c], d_lanep[6*1024+c]);
    float u3 = __fadd_rn(d_lanep[3*1024+c], d_lanep[7*1024+c]);
    float h0 = __fadd_rn(u0, u1);
    float h1 = __fadd_rn(u2, u3);
    float tot = __fadd_rn(h0, h1);
    d_m[l*1024 + c] = __fdiv_rn(tot, (float)cnt);
}

__global__ void bnfin2_kernel(int C, int cnt, int l){
    int c = blockIdx.x*blockDim.x + threadIdx.x;
    if (c >= C) return;
    float u0 = __fadd_rn(d_lanep[0*1024+c], d_lanep[4*1024+c]);
    float u1 = __fadd_rn(d_lanep[1*1024+c], d_lanep[5*1024+c]);
    float u2 = __fadd_rn(d_lanep[2*1024+c], d_lanep[6*1024+c]);
    float u3 = __fadd_rn(d_lanep[3*1024+c], d_lanep[7*1024+c]);
    float h0 = __fadd_rn(u0, u1);
    float h1 = __fadd_rn(u2, u3);
    float tot = __fadd_rn(h0, h1);
    float v = __fdiv_rn(tot, (float)cnt);
    d_r[l*1024 + c] = __fdiv_rn(1.f, __fsqrt_rn(__fadd_rn(v, 1e-5f)));
}

// ---- knn: unchanged (reference-order fp32) ------------------------------------
template<int C>
__global__ void __launch_bounds__(256) knn_kernel(const float* __restrict__ xt){
    extern __shared__ float sh[];
    float* qs = sh;
    float* ts = qs + C*33;
    float* dt = ts + C*129;
    float* tn = dt + 32*129;
    float* qn = tn + 128;
    float* mv = qn + 32;
    int*   mi = (int*)(mv + 32*8*KNN);

    int t  = threadIdx.x;
    int tx = t & 15, ty = t >> 4;
    int qbase = blockIdx.x * 32;
    int b = qbase >> 12;

    for (int e = t; e < 32*C; e += 256){
        int q = e / C, c = e % C;
        qs[c*33 + q] = xt[(size_t)(qbase + q)*C + c];
    }
    __syncthreads();
    if (t < 32){
        float s = 0.f;
        #pragma unroll
        for (int c = 0; c < C; c++){ float v = qs[c*33+t]; s = __fadd_rn(s, __fmul_rn(v,v)); }
        qn[t] = s;
    }

    int q = t >> 3, sub = t & 7;
    float bv[KNN]; int bi[KNN];
    #pragma unroll
    for (int u = 0; u < KNN; u++){ bv[u] = -3.4e38f; bi[u] = 0; }

    for (int m0 = 0; m0 < NN; m0 += 128){
        __syncthreads();
        for (int e = t; e < 128*C; e += 256){
            int ml = e / C, c = e % C;
            ts[c*129 + ml] = xt[(size_t)((b<<12) + m0 + ml)*C + c];
        }
        __syncthreads();
        if (t < 128){
            float s = 0.f;
            #pragma unroll
            for (int c = 0; c < C; c++){ float v = ts[c*129+t]; s = __fadd_rn(s, __fmul_rn(v,v)); }
            tn[t] = s;
        }
        __syncthreads();

        float acc0[8], acc1[8];
        #pragma unroll
        for (int j = 0; j < 8; j++){ acc0[j] = 0.f; acc1[j] = 0.f; }
        #pragma unroll 2
        for (int c = 0; c < C; c++){
            float qv0 = qs[c*33 + ty];
            float qv1 = qs[c*33 + ty + 16];
            #pragma unroll
            for (int j = 0; j < 8; j++){
                float m = ts[c*129 + tx + 16*j];
                acc0[j] = fmaf(qv0, m, acc0[j]);
                acc1[j] = fmaf(qv1, m, acc1[j]);
            }
        }
        {
            float qn0 = qn[ty], qn1 = qn[ty+16];
            #pragma unroll
            for (int j = 0; j < 8; j++){
                int mm = tx + 16*j;
                float tnm = tn[mm];
                dt[(ty)   *129 + mm] = __fadd_rn(fmaf(2.f, acc0[j], -qn0), -tnm);
                dt[(ty+16)*129 + mm] = __fadd_rn(fmaf(2.f, acc1[j], -qn1), -tnm);
            }
        }
        __syncthreads();

        #pragma unroll
        for (int j = 0; j < 16; j++){
            int ml = sub + 8*j;
            float v = dt[q*129 + ml];
            if (v > bv[KNN-1]){
                float cv = v; int ci = m0 + ml;
                #pragma unroll
                for (int u = 0; u < KNN; u++){
                    if (cv > bv[u]){
                        float tf = bv[u]; bv[u] = cv; cv = tf;
                        int   ti = bi[u]; bi[u] = ci; ci = ti;
                    }
                }
            }
        }
    }
    __syncthreads();
    {
        int base = (q*8 + sub)*KNN;
        #pragma unroll
        for (int u = 0; u < KNN; u++){ mv[base+u] = bv[u]; mi[base+u] = bi[u]; }
    }
    __syncthreads();
    if (sub == 0){
        int* hd = (int*)dt + q*8;
        #pragma unroll
        for (int j = 0; j < 8; j++) hd[j] = 0;
        for (int u = 0; u < KNN; u++){
            float best = -3.4e38f; int bidx = 0x7fffffff; int bl = 0;
            #pragma unroll
            for (int j = 0; j < 8; j++){
                int h = hd[j];
                if (h < KNN){
                    float av = mv[(q*8+j)*KNN + h];
                    int   ai = mi[(q*8+j)*KNN + h];
                    if (av > best || (av == best && ai < bidx)){ best = av; bidx = ai; bl = j; }
                }
            }
            d_nbr[(size_t)(qbase + q)*KNN + u] = bidx;
            hd[bl] = hd[bl] + 1;
        }
    }
}

// ---- tiled 1x1 conv, plain ascending-k fmaf (R10-proven) ----------------------
#define CTM 64
#define CTP 128
#define CKB 64

template<int MODE>
__global__ void __launch_bounds__(128) conv_kernel(
    const float* __restrict__ W, int Ktot, int Ototal,
    const float* __restrict__ in0, const float* __restrict__ in1,
    const float* __restrict__ in2, const float* __restrict__ in3,
    const float* __restrict__ ga, const float* __restrict__ ba,
    int Chalf, int actLayer, float* __restrict__ out)
{
    extern __shared__ float sh[];
    float* Ws = sh;
    float* Xs = sh + CKB*65;
    __shared__ int snbr[CTP];
    int t  = threadIdx.x;
    int tx = t & 15, ty = t >> 4;
    int gpBase = blockIdx.x * CTP;
    int oBase  = blockIdx.y * CTM;

    if (MODE == 0){
        if (t < 128) snbr[t] = d_nbr[gpBase + t];
    }

    float acc[8][8];
    #pragma unroll
    for (int i = 0; i < 8; i++)
        #pragma unroll
        for (int j = 0; j < 8; j++) acc[i][j] = 0.f;

    int nchunk = (Ktot + CKB - 1) / CKB;
    for (int ch = 0; ch < nchunk; ch++){
        int kc0 = ch * CKB;
        __syncthreads();
        for (int e = t; e < CKB*CTM; e += 128){
            int o = e >> 6, c = e & 63;
            int kc = kc0 + c;
            Ws[c*65 + o] = (kc < Ktot) ? W[(size_t)(oBase+o)*Ktot + kc] : 0.f;
        }
        for (int e = t; e < CKB*CTP; e += 128){
            int p = e >> 6, c = e & 63;
            int kc = kc0 + c;
            float v = 0.f;
            if (kc < Ktot){
                int gp = gpBase + p;
                if (MODE == 0){
                    int pn = gp / 20;
                    int bb = pn >> 12;
                    if (kc < Chalf){
                        int m = snbr[p];
                        v = in0[(size_t)((bb<<12) + m)*Chalf + kc];
                    } else {
                        v = in0[(size_t)pn*Chalf + (kc - Chalf)];
                    }
                } else if (MODE == 1){
                    float rr = in0[(size_t)gp*Ktot + kc];
                    v = actf(rr, d_m[actLayer*1024+kc], d_r[actLayer*1024+kc], ga[kc], ba[kc]);
                } else if (MODE == 2){
                    const float* src = (kc < 64) ? in0 : ((kc < 128) ? in1 : in2);
                    v = src[(size_t)gp*64 + (kc & 63)];
                } else {
                    if (kc < 1024){
                        int bb = gp >> 12;
                        v = in3[bb*1024 + kc];
                    } else {
                        int c2 = kc - 1024;
                        const float* src = (c2 < 64) ? in0 : ((c2 < 128) ? in1 : in2);
                        v = src[(size_t)gp*64 + (c2 & 63)];
                    }
                }
            }
            Xs[c*129 + p] = v;
        }
        __syncthreads();
        #pragma unroll 4
        for (int k = 0; k < CKB; k++){
            float xv[8], wv[8];
            #pragma unroll
            for (int j = 0; j < 8; j++) xv[j] = Xs[k*129 + tx + 16*j];
            #pragma unroll
            for (int i = 0; i < 8; i++) wv[i] = Ws[k*65 + ty + 8*i];
            #pragma unroll
            for (int i = 0; i < 8; i++)
                #pragma unroll
                for (int j = 0; j < 8; j++)
                    acc[i][j] = fmaf(wv[i], xv[j], acc[i][j]);
        }
    }

    __syncthreads();
    float* outS = sh;
    #pragma unroll
    for (int j = 0; j < 8; j++)
        #pragma unroll
        for (int i = 0; i < 8; i++)
            outS[(tx + 16*j)*65 + ty + 8*i] = acc[i][j];
    __syncthreads();
    for (int e = t; e < CTP*CTM; e += 128){
        int p = e >> 6, o = e & 63;
        out[(size_t)(gpBase+p)*Ototal + oBase + o] = outS[p*65 + o];
    }
}

__global__ void maxk_kernel(const float* __restrict__ y, int l,
                            const float* __restrict__ gl, const float* __restrict__ bl,
                            float* __restrict__ xt){
    int t = threadIdx.x;
    int p = blockIdx.x*4 + (t >> 6);
    int o = t & 63;
    float m = d_m[l*1024+o], r = d_r[l*1024+o];
    float gv = gl[o], bvv = bl[o];
    const float* base = y + (size_t)p*KNN*64 + o;
    float mx = -3.4e38f;
    #pragma unroll
    for (int kk = 0; kk < KNN; kk++){
        float v = actf(base[kk*64], m, r, gv, bvv);
        mx = fmaxf(mx, v);
    }
    xt[(size_t)p*64 + o] = mx;
}

__global__ void gmax_kernel(const float* __restrict__ y6, int l,
                            const float* __restrict__ gl, const float* __restrict__ bl){
    int bb = blockIdx.x >> 4, grp = blockIdx.x & 15;
    int t = threadIdx.x;
    int o = grp*64 + (t & 63);
    float m = d_m[l*1024+o], r = d_r[l*1024+o];
    float gv = gl[o], bvv = bl[o];
    float mx = -3.4e38f;
    for (int n = (t >> 6); n < NN; n += 4){
        float v = actf(y6[((size_t)(bb*NN+n))*1024 + o], m, r, gv, bvv);
        mx = fmaxf(mx, v);
    }
    __shared__ float red[256];
    red[t] = mx;
    __syncthreads();
    if (t < 64){
        float mm = fmaxf(fmaxf(red[t], red[t+64]), fmaxf(red[t+128], red[t+192]));
        d_gmaxv[bb*1024 + o] = mm;
    }
}

__global__ void __launch_bounds__(128) final_kernel(const float* __restrict__ W9,
                                                    const float* __restrict__ y8,
                                                    const float* __restrict__ gl,
                                                    const float* __restrict__ bl,
                                                    float* __restrict__ out){
    __shared__ float Ws[13*64];
    __shared__ float Xs[64*129];
    int t = threadIdx.x;
    int pBase = blockIdx.x * 128;
    float acc[13];
    #pragma unroll
    for (int o = 0; o < 13; o++) acc[o] = 0.f;

    for (int ch = 0; ch < 4; ch++){
        __syncthreads();
        for (int e = t; e < 13*64; e += 128){
            int o = e >> 6, c = e & 63;
            Ws[e] = W9[o*256 + ch*64 + c];
        }
        for (int e = t; e < 64*128; e += 128){
            int p = e >> 6, c = e & 63;
            int kc = ch*64 + c;
            float rr = y8[(size_t)(pBase+p)*256 + kc];
            Xs[c*129 + p] = actf(rr, d_m[7*1024 + kc], d_r[7*1024 + kc], gl[kc], bl[kc]);
        }
        __syncthreads();
        #pragma unroll 4
        for (int k = 0; k < 64; k++){
            float xv = Xs[k*129 + t];
            #pragma unroll
            for (int o = 0; o < 13; o++)
                acc[o] = fmaf(Ws[o*64 + k], xv, acc[o]);
        }
    }
    int pn = pBase + t;
    int b = pn >> 12, n = pn & (NN-1);
    #pragma unroll
    for (int o = 0; o < 13; o++)
        out[(size_t)b*13*NN + (size_t)o*NN + n] = acc[o];
}

extern "C" void kernel_launch(void* const* d_in, const int* in_sizes, int n_in,
                              void* d_out, int out_size) {
    const float* xyz  = (const float*)d_in[0];
    const float* feat = (const float*)d_in[1];
    const float* W1 = (const float*)d_in[2];
    const float* W2 = (const float*)d_in[3];
    const float* W3 = (const float*)d_in[4];
    const float* W4 = (const float*)d_in[5];
    const float* W5 = (const float*)d_in[6];
    const float* W6 = (const float*)d_in[7];
    const float* W7 = (const float*)d_in[8];
    const float* W8 = (const float*)d_in[9];
    const float* W9 = (const float*)d_in[10];
    const float* g[8]; const float* bb[8];
    for (int i = 0; i < 8; i++){ g[i] = (const float*)d_in[11+2*i]; bb[i] = (const float*)d_in[12+2*i]; }
    float* out = (float*)d_out;

    float *x0t, *x1t, *x2t, *x3t, *bufA, *bufB, *gmx;
    cudaGetSymbolAddress((void**)&x0t,  d_x0t);
    cudaGetSymbolAddress((void**)&x1t,  d_x1t);
    cudaGetSymbolAddress((void**)&x2t,  d_x2t);
    cudaGetSymbolAddress((void**)&x3t,  d_x3t);
    cudaGetSymbolAddress((void**)&bufA, d_bufA);
    cudaGetSymbolAddress((void**)&bufB, d_bufB);
    cudaGetSymbolAddress((void**)&gmx,  d_gmaxv);

    const int SH_KNN6  = (6*33  + 6*129  + 32*129 + 128 + 32 + 32*8*KNN)*4 + 32*8*KNN*4;
    const int SH_KNN64 = (64*33 + 64*129 + 32*129 + 128 + 32 + 32*8*KNN)*4 + 32*8*KNN*4;
    const int SH_CONV  = (CKB*65 + CKB*129)*4;
    const int SH_STAT  = 2*SCH*32*4;   // 65536

    cudaFuncSetAttribute(knn_kernel<6>,  cudaFuncAttributeMaxDynamicSharedMemorySize, SH_KNN6);
    cudaFuncSetAttribute(knn_kernel<64>, cudaFuncAttributeMaxDynamicSharedMemorySize, SH_KNN64);
    cudaFuncSetAttribute(conv_kernel<0>, cudaFuncAttributeMaxDynamicSharedMemorySize, SH_CONV);
    cudaFuncSetAttribute(conv_kernel<1>, cudaFuncAttributeMaxDynamicSharedMemorySize, SH_CONV);
    cudaFuncSetAttribute(conv_kernel<2>, cudaFuncAttributeMaxDynamicSharedMemorySize, SH_CONV);
    cudaFuncSetAttribute(conv_kernel<3>, cudaFuncAttributeMaxDynamicSharedMemorySize, SH_CONV);
    cudaFuncSetAttribute(bnstat1_kernel, cudaFuncAttributeMaxDynamicSharedMemorySize, SH_STAT);
    cudaFuncSetAttribute(bnstat2_kernel, cudaFuncAttributeMaxDynamicSharedMemorySize, SH_STAT);

    dim3 gEdge(NPK/CTP, 1);

    pack_kernel<<<(NPT*6+255)/256, 256>>>(xyz, feat);

    #define BNSTATS(buf_, C_, cnt_, l_) \
        bnstat1_kernel<<<(C_/32)*8, 256, SH_STAT>>>(buf_, C_, cnt_, l_); \
        bnfin1_kernel<<<(C_+63)/64, 64>>>(C_, cnt_, l_); \
        bnstat2_kernel<<<(C_/32)*8, 256, SH_STAT>>>(buf_, C_, cnt_, l_); \
        bnfin2_kernel<<<(C_+63)/64, 64>>>(C_, cnt_, l_)

    knn_kernel<6><<<NPT/32, 256, SH_KNN6>>>(x0t);
    conv_kernel<0><<<gEdge, 128, SH_CONV>>>(W1, 12, 64, x0t, 0,0,0, 0,0, 6, 0, bufA);
    BNSTATS(bufA, 64, NPK, 0);
    conv_kernel<1><<<gEdge, 128, SH_CONV>>>(W2, 64, 64, bufA, 0,0,0, g[0], bb[0], 0, 0, bufB);
    BNSTATS(bufB, 64, NPK, 1);
    maxk_kernel<<<NPT/4, 256>>>(bufB, 1, g[1], bb[1], x1t);

    knn_kernel<64><<<NPT/32, 256, SH_KNN64>>>(x1t);
    conv_kernel<0><<<gEdge, 128, SH_CONV>>>(W3, 128, 64, x1t, 0,0,0, 0,0, 64, 0, bufA);
    BNSTATS(bufA, 64, NPK, 2);
    conv_kernel<1><<<gEdge, 128, SH_CONV>>>(W4, 64, 64, bufA, 0,0,0, g[2], bb[2], 0, 2, bufB);
    BNSTATS(bufB, 64, NPK, 3);
    maxk_kernel<<<NPT/4, 256>>>(bufB, 3, g[3], bb[3], x2t);

    knn_kernel<64><<<NPT/32, 256, SH_KNN64>>>(x2t);
    conv_kernel<0><<<gEdge, 128, SH_CONV>>>(W5, 128, 64, x2t, 0,0,0, 0,0, 64, 0, bufA);
    BNSTATS(bufA, 64, NPK, 4);
    maxk_kernel<<<NPT/4, 256>>>(bufA, 4, g[4], bb[4], x3t);

    conv_kernel<2><<<dim3(NPT/CTP, 16), 128, SH_CONV>>>(W6, 192, 1024, x1t, x2t, x3t, 0, 0,0, 0, 0, bufB);
    BNSTATS(bufB, 1024, NPT, 5);
    gmax_kernel<<<NB*16, 256>>>(bufB, 5, g[5], bb[5]);

    conv_kernel<3><<<dim3(NPT/CTP, 8), 128, SH_CONV>>>(W7, 1216, 512, x1t, x2t, x3t, gmx, 0,0, 0, 0, bufA);
    BNSTATS(bufA, 512, NPT, 6);
    conv_kernel<1><<<dim3(NPT/CTP, 4), 128, SH_CONV>>>(W8, 512, 256, bufA, 0,0,0, g[6], bb[6], 0, 6, bufB);
    BNSTATS(bufB, 256, NPT, 7);
    final_kernel<<<NPT/128, 128>>>(W9, bufB, g[7], bb[7], out);
}